// round 6
// baseline (speedup 1.0000x reference)
#include <cuda_runtime.h>

#define BSZ  512
#define NN   128
#define NMAT 2560
#define SS   132             // stage row stride (words): 132 ≡ 4 (mod 32)

// ---------------- packed f32x2 helpers (Blackwell) --------------------------
__device__ __forceinline__ unsigned long long pk2(float lo, float hi) {
    unsigned long long r;
    asm("mov.b64 %0, {%1, %2};" : "=l"(r) : "f"(lo), "f"(hi));
    return r;
}
__device__ __forceinline__ void up2(unsigned long long p, float& lo, float& hi) {
    asm("mov.b64 {%0, %1}, %2;" : "=f"(lo), "=f"(hi) : "l"(p));
}
__device__ __forceinline__ unsigned long long add2(unsigned long long a,
                                                   unsigned long long b) {
    unsigned long long r;
    asm("add.rn.f32x2 %0, %1, %2;" : "=l"(r) : "l"(a), "l"(b));
    return r;
}
__device__ __forceinline__ unsigned long long mul2(unsigned long long a,
                                                   unsigned long long b) {
    unsigned long long r;
    asm("mul.rn.f32x2 %0, %1, %2;" : "=l"(r) : "l"(a), "l"(b));
    return r;
}

// ---------------- persistent scratch (__device__ globals) -------------------
__device__ float g_Ts[128];
__device__ int   g_perm[128];
__device__ float g_A [129 * 128];
__device__ float g_Cc[129 * 128];
__device__ int   g_kidx[BSZ * NN];

// ---------------- kernel 1: rank thresholds ---------------------------------
__global__ void k_rank(const float* __restrict__ w1, const float* __restrict__ b1)
{
    __shared__ float tsh[128];
    int l = threadIdx.x;
    float w  = w1[l];
    float bb = b1[l];
    float tv;
    if (w != 0.0f) tv = -bb / w;
    else           tv = (bb > 0.0f) ? -3.0e38f : 3.0e38f;
    tsh[l] = tv;
    __syncthreads();
    int r = 0;
    for (int p = 0; p < 128; ++p) {
        float o = tsh[p];
        r += (o < tv) || (o == tv && p < l);
    }
    g_Ts[r]   = tv;
    g_perm[r] = l;
}

// ---------------- kernel 2: interval tables ---------------------------------
__global__ void k_tables(const float* __restrict__ w1, const float* __restrict__ b1,
                         const float* __restrict__ w2, const float* __restrict__ b2)
{
    __shared__ float ws[128], bs[128];
    __shared__ int   ps[128];
    int k = blockIdx.x;       // 0..128
    int j = threadIdx.x;      // 0..127
    ps[j] = g_perm[j];
    __syncthreads();
    ws[j] = w1[ps[j]];
    bs[j] = b1[ps[j]];
    __syncthreads();
    float a = 0.f, c = 0.f;
    #pragma unroll 4
    for (int p = 0; p < 128; ++p) {
        float w  = ws[p];
        float bb = bs[p];
        bool pos = (w > 0.f) || (w == 0.f && bb > 0.f);
        bool act = pos ? (p < k) : (p >= k);
        if (act) {
            float wv = w2[j * 128 + ps[p]];
            a = fmaf(w,  wv, a);
            c = fmaf(bb, wv, c);
        }
    }
    g_A [k * 128 + j] = a;
    g_Cc[k * 128 + j] = c + b2[j];
}

// ---------------- kernel 3: interval index per scalar -----------------------
__global__ void k_kidx(const float* __restrict__ x)
{
    int i = blockIdx.x * blockDim.x + threadIdx.x;
    if (i >= BSZ * NN) return;
    float xv = x[i];
    int lo = 0, hi = 128;
    while (lo < hi) {
        int mid = (lo + hi) >> 1;
        if (g_Ts[mid] < xv) lo = mid + 1; else hi = mid;
    }
    g_kidx[i] = lo;
}

// ---------------- kernel 4: register-resident evolving Sinkhorn -------------
// warp w: g=w>>2 (row group), q=w&3 (column quarter); lane -> row r=32g+lane.
// Register slice is column-PERMUTED: rr.f[cb+j] = M[r][32q+cb+(j^msw)],
// msw = (lane>>1)&12, so butterfly stages off=16/off=8 are select-free.
__global__ __launch_bounds__(512, 2) void k_sinkhorn(
    const float* __restrict__ x,
    const float* __restrict__ noise,
    float* __restrict__ out)
{
    extern __shared__ float sm[];
    float* stage = sm;                    // [128][SS]
    float* P2    = sm + 128 * SS;         // [4][SS]  col partials
    float* P1    = P2 + 4 * SS;           // [128*5]  row partials (stride 5)
    float* Cv    = P1 + 128 * 5;          // [128]
    float* xs    = Cv + 128;              // [128]
    int*   ks    = (int*)(xs + 128);      // [128]

    const int m    = blockIdx.x;
    const int b    = m & (BSZ - 1);
    const int tid  = threadIdx.x;
    const int lane = tid & 31;
    const int wrp  = tid >> 5;
    const int g    = wrp >> 2;
    const int q    = wrp & 3;
    const int r    = 32 * g + lane;
    const int msw  = (lane >> 1) & 12;

    if (tid < 128) {
        xs[tid] = x[b * NN + tid];
        ks[tid] = g_kidx[b * NN + tid];
    }
    __syncthreads();

    // ---- prologue: build M0 into stage[row][col], fully coalesced ----------
    const float* nzm = noise + (size_t)m * (NN * NN);
    #pragma unroll
    for (int h = 0; h < 8; ++h) {
        int id  = h * 512 + tid;          // float4 index; row uniform per warp
        int row = id >> 5;
        int c4  = (id & 31) * 4;
        int   kr = ks[row];
        float xv = xs[row];
        float4 a4 = *(const float4*)(g_A  + kr * 128 + c4);
        float4 q4 = *(const float4*)(g_Cc + kr * 128 + c4);
        float4 n4 = *(const float4*)(nzm + id * 4);
        float4 e;
        e.x = __expf(fmaf(a4.x, xv, q4.x) + n4.x);
        e.y = __expf(fmaf(a4.y, xv, q4.y) + n4.y);
        e.z = __expf(fmaf(a4.z, xv, q4.z) + n4.z);
        e.w = __expf(fmaf(a4.w, xv, q4.w) + n4.w);
        *(float4*)(stage + row * SS + c4) = e;
    }
    __syncthreads();

    // ---- pick up permuted row slice into registers -------------------------
    union Slice { float f[32]; float4 v4[8]; unsigned long long u2[16]; };
    Slice rr;
    #pragma unroll
    for (int t = 0; t < 8; ++t)
        rr.v4[t] = *(const float4*)(stage + r * SS + 32 * q + ((4 * t) ^ msw));

    // ---- 10 evolving-Sinkhorn iterations -----------------------------------
    for (int it = 0; it < 10; ++it) {
        // (1) row sum (packed tree) -> partial
        unsigned long long s8[8];
        #pragma unroll
        for (int k = 0; k < 8; ++k) s8[k] = add2(rr.u2[k], rr.u2[k + 8]);
        #pragma unroll
        for (int k = 0; k < 4; ++k) s8[k] = add2(s8[k], s8[k + 4]);
        s8[0] = add2(s8[0], s8[1]);
        s8[2] = add2(s8[2], s8[3]);
        s8[0] = add2(s8[0], s8[2]);
        float slo, shi; up2(s8[0], slo, shi);
        P1[r * 5 + q] = slo + shi;
        __syncthreads();

        // (2) every thread re-derives R for its row; scale rows in place
        float rs = (P1[r * 5 + 0] + P1[r * 5 + 1]) +
                   (P1[r * 5 + 2] + P1[r * 5 + 3]);
        float R_own = __fdividef(1.0f, rs);
        unsigned long long R22 = pk2(R_own, R_own);
        #pragma unroll
        for (int k = 0; k < 16; ++k) rr.u2[k] = mul2(rr.u2[k], R22);

        // (3) column sums: two select-light butterfly passes over warp rows
        #pragma unroll
        for (int pass = 0; pass < 2; ++pass) {
            const int cb = 16 * pass;
            float w8[8];
            #pragma unroll
            for (int j = 0; j < 8; ++j)     // col bit3 <- lane bit4 (pre-swizzled)
                w8[j] = rr.f[cb + j] +
                        __shfl_xor_sync(0xffffffffu, rr.f[cb + j + 8], 16);
            float w4[4];
            #pragma unroll
            for (int j = 0; j < 4; ++j)     // col bit2 <- lane bit3 (pre-swizzled)
                w4[j] = w8[j] + __shfl_xor_sync(0xffffffffu, w8[j + 4], 8);
            float w2v[2];
            bool u4 = (lane & 4) != 0;      // col bit1 <- lane bit2 (select)
            #pragma unroll
            for (int j = 0; j < 2; ++j) {
                float sd = u4 ? w4[j] : w4[j + 2];
                float kp = u4 ? w4[j + 2] : w4[j];
                w2v[j] = kp + __shfl_xor_sync(0xffffffffu, sd, 4);
            }
            bool u2b = (lane & 2) != 0;     // col bit0 <- lane bit1 (select)
            float sd = u2b ? w2v[0] : w2v[1];
            float kp = u2b ? w2v[1] : w2v[0];
            float w1 = kp + __shfl_xor_sync(0xffffffffu, sd, 2);
            float v  = w1 + __shfl_xor_sync(0xffffffffu, w1, 1);  // rows: lane bit0
            if (!(lane & 1))
                P2[g * SS + 32 * q + cb + ((lane >> 1) & 15)] = v;
        }
        __syncthreads();

        // (4) reduce column partials -> Cv
        if (tid < 128)
            Cv[tid] = __fdividef(1.0f, (P2[tid] + P2[SS + tid]) +
                                        (P2[2 * SS + tid] + P2[3 * SS + tid]));
        __syncthreads();

        // (5) scale columns in place (swizzle-aligned vec4 broadcast)
        #pragma unroll
        for (int t = 0; t < 8; ++t) {
            float4 c4 = *(const float4*)(Cv + 32 * q + ((4 * t) ^ msw));
            rr.u2[2 * t]     = mul2(rr.u2[2 * t],     pk2(c4.x, c4.y));
            rr.u2[2 * t + 1] = mul2(rr.u2[2 * t + 1], pk2(c4.z, c4.w));
        }
    }

    // ---- epilogue: registers already hold final M; transpose via stage -----
    #pragma unroll
    for (int t = 0; t < 8; ++t) {
        int col = 32 * q + ((4 * t) ^ msw);
        stage[(col + 0) * SS + r] = rr.f[4 * t + 0];
        stage[(col + 1) * SS + r] = rr.f[4 * t + 1];
        stage[(col + 2) * SS + r] = rr.f[4 * t + 2];
        stage[(col + 3) * SS + r] = rr.f[4 * t + 3];
    }
    __syncthreads();
    float* om = out + (size_t)m * (NN * NN);
    #pragma unroll
    for (int h = 0; h < 8; ++h) {
        int id  = h * 512 + tid;
        int row = id >> 5;
        int c4  = (id & 31) * 4;
        *(float4*)(om + id * 4) = *(const float4*)(stage + row * SS + c4);
    }
}

// ---------------- launch ----------------------------------------------------
extern "C" void kernel_launch(void* const* d_in, const int* in_sizes, int n_in,
                              void* d_out, int out_size)
{
    const float* x     = (const float*)d_in[0];
    const float* w1    = (const float*)d_in[1];
    const float* b1    = (const float*)d_in[2];
    const float* w2    = (const float*)d_in[3];
    const float* b2    = (const float*)d_in[4];
    const float* noise = (const float*)d_in[5];
    float* out = (float*)d_out;

    k_rank  <<<1,   128>>>(w1, b1);
    k_tables<<<129, 128>>>(w1, b1, w2, b2);
    k_kidx  <<<256, 256>>>(x);

    // stage + P2 + P1 + Cv + xs + ks
    const int smem_words = 128 * SS + 4 * SS + 128 * 5 + 128 + 128 + 128;
    const int smem_bytes = smem_words * 4;               // 73,792 B
    cudaFuncSetAttribute(k_sinkhorn, cudaFuncAttributeMaxDynamicSharedMemorySize,
                         smem_bytes);
    k_sinkhorn<<<NMAT, 512, smem_bytes>>>(x, noise, out);
}